// round 14
// baseline (speedup 1.0000x reference)
#include <cuda_runtime.h>
#include <math.h>

#define NTOK   49
#define CDIM   256
#define HEADS  8
#define HD     32
#define BMAX   2048
#define NN2    2401   // 49*49
#define BMSZ   2452   // 49 rows x 50 (padded) + 2 pad -> 16B multiple
#define NWMAX  64
#define MMAX   (BMAX * NTOK)
#define SPAD   40     // GEMM smem row pad for BK=32 (conflict-free LDS.64)

// Scratch (allocation-free: __device__ globals)
// g_xr / g_wqr / g_wpr / g_att use the within-8 permutation p=(k&3)*2+(k>>2)
__device__ float g_qkv[MMAX * 768];             // [M][768] natural layout
__device__ float g_att[MMAX * CDIM];            // [M][256] PERMUTED + tf32
__device__ float g_xr[MMAX * CDIM];             // PERMUTED + tf32 x
__device__ float g_wqr[768 * 256];              // PERMUTED + tf32 qkv_w
__device__ float g_wpr[256 * 256];              // PERMUTED + tf32 proj_w
__device__ float g_t8[169 * 8];                 // raw CPB MLP output [r][h]
__device__ float g_bm[NWMAX * HEADS * BMSZ];    // 16*sigmoid(bias)+mask, rows of 50

__device__ __forceinline__ float tf32r(float x) {
    unsigned u;
    asm("cvt.rna.tf32.f32 %0, %1;" : "=r"(u) : "f"(x));
    return __uint_as_float(u);
}

__device__ __forceinline__ void mma_tf32(float* c, const unsigned* a, const unsigned* b) {
    asm volatile(
        "mma.sync.aligned.m16n8k8.row.col.f32.tf32.tf32.f32 "
        "{%0,%1,%2,%3}, {%4,%5,%6,%7}, {%8,%9}, {%0,%1,%2,%3};"
        : "+f"(c[0]), "+f"(c[1]), "+f"(c[2]), "+f"(c[3])
        : "r"(a[0]), "r"(a[1]), "r"(a[2]), "r"(a[3]), "r"(b[0]), "r"(b[1]));
}

#define CPA16(dst_u32, src_ptr) \
    asm volatile("cp.async.cg.shared.global [%0], [%1], 16;" :: "r"(dst_u32), "l"(src_ptr))

// interleave two float4 k-groups into permuted order
__device__ __forceinline__ void perm_store8(float* dst, float4 lo, float4 hi) {
    float4 o0 = make_float4(tf32r(lo.x), tf32r(hi.x), tf32r(lo.y), tf32r(hi.y));
    float4 o1 = make_float4(tf32r(lo.z), tf32r(hi.z), tf32r(lo.w), tf32r(hi.w));
    ((float4*)dst)[0] = o0;
    ((float4*)dst)[1] = o1;
}

// ---------------------------------------------------------------------------
// tf32 pre-round + permute passes
// ---------------------------------------------------------------------------
__global__ void round_x_kernel(const float* __restrict__ x, int n8)
{
    const int stride = gridDim.x * blockDim.x;
    for (int i = blockIdx.x * blockDim.x + threadIdx.x; i < n8; i += stride) {
        const float4 lo = ((const float4*)x)[2 * i];
        const float4 hi = ((const float4*)x)[2 * i + 1];
        perm_store8(&g_xr[8 * (size_t)i], lo, hi);
    }
}

__global__ void round_w_kernel(const float* __restrict__ qkv_w,
                               const float* __restrict__ proj_w)
{
    const int stride = gridDim.x * blockDim.x;
    const int nq = 768 * 256 / 8, np = 256 * 256 / 8;
    for (int i = blockIdx.x * blockDim.x + threadIdx.x; i < nq + np; i += stride) {
        if (i < nq) {
            const float4 lo = ((const float4*)qkv_w)[2 * i];
            const float4 hi = ((const float4*)qkv_w)[2 * i + 1];
            perm_store8(&g_wqr[8 * (size_t)i], lo, hi);
        } else {
            const int j = i - nq;
            const float4 lo = ((const float4*)proj_w)[2 * j];
            const float4 hi = ((const float4*)proj_w)[2 * j + 1];
            perm_store8(&g_wpr[8 * (size_t)j], lo, hi);
        }
    }
}

// ---------------------------------------------------------------------------
// CPB MLP, parallel: one warp per (row r, head hh). 169 blocks x 8 warps.
// ---------------------------------------------------------------------------
__global__ void cpb_kernel(const float* __restrict__ table,
                           const float* __restrict__ w1,
                           const float* __restrict__ b1,
                           const float* __restrict__ w2)
{
    const int r = blockIdx.x;
    const int hh = threadIdx.x >> 5;
    const int lane = threadIdx.x & 31;
    const float t0 = table[r * 2 + 0];
    const float t1 = table[r * 2 + 1];
    float s = 0.f;
#pragma unroll
    for (int it = 0; it < 16; ++it) {
        const int j = lane + it * 32;
        float hv = fmaf(t0, w1[j * 2 + 0], fmaf(t1, w1[j * 2 + 1], b1[j]));
        hv = fmaxf(hv, 0.f);
        s = fmaf(hv, w2[hh * 512 + j], s);
    }
#pragma unroll
    for (int o = 16; o > 0; o >>= 1)
        s += __shfl_xor_sync(0xffffffffu, s, o);
    if (lane == 0) g_t8[r * 8 + hh] = s;
}

// g_bm[wi*H+h][r*50+c] = 16*sigmoid(g_t8[idx[r*49+c]][h]) + mask[wi][r*49+c]
__global__ void bm_kernel(const float* __restrict__ mask,
                          const int* __restrict__ idx)
{
    __shared__ float t8s[169 * 8];
    const int wi = blockIdx.x / HEADS, h = blockIdx.x % HEADS;
    for (int i = threadIdx.x; i < 169 * 8; i += blockDim.x)
        t8s[i] = g_t8[i];
    __syncthreads();
    const float* mp = mask + (size_t)wi * NN2;
    float* o = g_bm + (size_t)blockIdx.x * BMSZ;
    for (int i = threadIdx.x; i < BMSZ; i += blockDim.x) {
        const int r = i / 50, c = i % 50;
        if (r < 49 && c < 49) {
            const float bv = t8s[idx[r * 49 + c] * 8 + h];
            o[i] = 16.f / (1.f + __expf(-bv)) + mp[r * 49 + c];
        } else {
            o[i] = 0.f;
        }
    }
}

// ---------------------------------------------------------------------------
// 2-stage cp.async tf32 GEMM, 512 threads, BK=32 (half the syncs).
// Operands pre-rounded + permuted in gmem -> fragment loads are LDS.64.
// ---------------------------------------------------------------------------
#define GEMM_PIPE(XPTR, WPTR)                                                     \
    __shared__ float As[2][128][SPAD];                                            \
    __shared__ float Bs[2][128][SPAD];                                            \
    const int tid = threadIdx.x;                                                  \
    const int lane = tid & 31, wid = tid >> 5;                                    \
    const int g = lane >> 2, tg = lane & 3;                                       \
    const int wm = (wid & 3) * 32, wn = (wid >> 2) * 32;                          \
    const int m0 = blockIdx.y * 128, n0 = blockIdx.x * 128;                       \
    const int lrow = tid >> 2, lcol = (tid & 3) * 4;                              \
    const float* gA0 = (XPTR) + (size_t)(m0 + lrow) * 256 + lcol;                 \
    const float* gB0 = (WPTR) + (size_t)(n0 + lrow) * 256 + lcol;                 \
    const unsigned sA = (unsigned)__cvta_generic_to_shared(&As[0][lrow][lcol]);   \
    const unsigned sB = (unsigned)__cvta_generic_to_shared(&Bs[0][lrow][lcol]);   \
    const unsigned STG = 128 * SPAD * 4;                                          \
    float acc[2][4][4];                                                           \
    _Pragma("unroll") for (int i = 0; i < 2; ++i)                                 \
    _Pragma("unroll") for (int j = 0; j < 4; ++j)                                 \
    _Pragma("unroll") for (int r = 0; r < 4; ++r) acc[i][j][r] = 0.f;             \
    CPA16(sA,      gA0);                                                          \
    CPA16(sA + 64, gA0 + 16);                                                     \
    CPA16(sB,      gB0);                                                          \
    CPA16(sB + 64, gB0 + 16);                                                     \
    asm volatile("cp.async.commit_group;");                                       \
    for (int kb = 0; kb < 8; ++kb) {                                              \
        if (kb < 7) {                                                             \
            const unsigned so = (unsigned)((kb + 1) & 1) * STG;                   \
            const int kOff = (kb + 1) * 32;                                       \
            CPA16(sA + so,      gA0 + kOff);                                      \
            CPA16(sA + so + 64, gA0 + kOff + 16);                                 \
            CPA16(sB + so,      gB0 + kOff);                                      \
            CPA16(sB + so + 64, gB0 + kOff + 16);                                 \
            asm volatile("cp.async.commit_group;");                               \
            asm volatile("cp.async.wait_group 1;");                               \
        } else {                                                                  \
            asm volatile("cp.async.wait_group 0;");                               \
        }                                                                         \
        __syncthreads();                                                          \
        const int s = kb & 1;                                                     \
        _Pragma("unroll") for (int ks = 0; ks < 4; ++ks) {                        \
            const int kk = ks * 8;                                                \
            unsigned af[2][4], bf[4][2];                                          \
            _Pragma("unroll") for (int mi = 0; mi < 2; ++mi) {                    \
                const int r = wm + mi * 16 + g;                                   \
                const float2 aA = *(const float2*)&As[s][r    ][kk + tg * 2];     \
                const float2 aB = *(const float2*)&As[s][r + 8][kk + tg * 2];     \
                af[mi][0] = __float_as_uint(aA.x);                                \
                af[mi][1] = __float_as_uint(aB.x);                                \
                af[mi][2] = __float_as_uint(aA.y);                                \
                af[mi][3] = __float_as_uint(aB.y);                                \
            }                                                                     \
            _Pragma("unroll") for (int ni = 0; ni < 4; ++ni) {                    \
                const int c = wn + ni * 8 + g;                                    \
                const float2 bB = *(const float2*)&Bs[s][c][kk + tg * 2];         \
                bf[ni][0] = __float_as_uint(bB.x);                                \
                bf[ni][1] = __float_as_uint(bB.y);                                \
            }                                                                     \
            _Pragma("unroll") for (int mi = 0; mi < 2; ++mi)                      \
            _Pragma("unroll") for (int ni = 0; ni < 4; ++ni)                      \
                mma_tf32(acc[mi][ni], af[mi], bf[ni]);                            \
        }                                                                         \
        __syncthreads();                                                          \
    }

__device__ __forceinline__ float qkvb(int o, const float* qb, const float* vb) {
    return (o < 256) ? qb[o] : ((o < 512) ? 0.f : vb[o - 512]);
}

__global__ __launch_bounds__(512, 2) void mma_qkv(const float* __restrict__ qb,
                                                  const float* __restrict__ vb)
{
    GEMM_PIPE(g_xr, g_wqr)
#pragma unroll
    for (int mi = 0; mi < 2; ++mi) {
        const int mA = m0 + wm + mi * 16 + g;
#pragma unroll
        for (int ni = 0; ni < 4; ++ni) {
            const int o = n0 + wn + ni * 8 + tg * 2;
            const float b0 = qkvb(o, qb, vb), b1 = qkvb(o + 1, qb, vb);
            float2 v0 = make_float2(acc[mi][ni][0] + b0, acc[mi][ni][1] + b1);
            float2 v1 = make_float2(acc[mi][ni][2] + b0, acc[mi][ni][3] + b1);
            *(float2*)&g_qkv[(size_t)mA * 768 + o]       = v0;
            *(float2*)&g_qkv[(size_t)(mA + 8) * 768 + o] = v1;
        }
    }
}

__global__ __launch_bounds__(512, 2) void mma_proj(const float* __restrict__ pb,
                                                   float* __restrict__ out)
{
    GEMM_PIPE(g_att, g_wpr)
#pragma unroll
    for (int mi = 0; mi < 2; ++mi) {
        const int mA = m0 + wm + mi * 16 + g;
#pragma unroll
        for (int ni = 0; ni < 4; ++ni) {
            const int o = n0 + wn + ni * 8 + tg * 2;
            const float b0 = pb[o], b1 = pb[o + 1];
            float2 v0 = make_float2(acc[mi][ni][0] + b0, acc[mi][ni][1] + b1);
            float2 v1 = make_float2(acc[mi][ni][2] + b0, acc[mi][ni][3] + b1);
            *(float2*)&out[(size_t)mA * 256 + o]       = v0;
            *(float2*)&out[(size_t)(mA + 8) * 256 + o] = v1;
        }
    }
}

// ---------------------------------------------------------------------------
// MMA attention. One block per (b,h), 4 warps. ps and vt stored PERMUTED
// (within-8) so AV fragment loads are LDS.64; bias loads are aligned float2.
// smem: qk2 37.9K + vt 9.2K + bms 9.8K = 56.9K -> 4 CTAs/SM.
// ---------------------------------------------------------------------------
__global__ __launch_bounds__(128, 4) void attn_mma(const float* __restrict__ logit_scale,
                                                   int nW)
{
    __shared__ float2 qk2[2][64][37];   // [0]=q, [1]=k; (hi, lo)
    __shared__ float  vt[32][72];       // V^T, tf32, token-permuted
    __shared__ float  bms[BMSZ];        // bias+mask tile, rows of 50
    float* ps = (float*)qk2;            // [64][72] alias, col-permuted

    const int b = blockIdx.x, h = blockIdx.y;
    const int tid = threadIdx.x, w = tid >> 5, lane = tid & 31;
    const int g = lane >> 2, tg = lane & 3;
    const int wm = w * 16;
    const float scale = __expf(fminf(logit_scale[h], 4.605170185988092f)); // ln(100)

    // permuted positions for cols tg*2, tg*2+1 within an 8-group
    const int j0 = tg * 2, j1 = j0 + 1;
    const int pp0 = (j0 & 3) * 2 + (j0 >> 2);
    const int pp1 = (j1 & 3) * 2 + (j1 >> 2);

    // kick off bias+mask DMA first (613 x 16B)
    {
        const float* bmg = &g_bm[(size_t)((b % nW) * HEADS + h) * BMSZ];
        const unsigned sbm = (unsigned)__cvta_generic_to_shared(bms);
        for (int i = tid; i < BMSZ / 4; i += 128)
            CPA16(sbm + i * 16, bmg + i * 4);
        asm volatile("cp.async.commit_group;");
    }

    // zero token padding
    for (int i = tid; i < 2 * 15 * 37; i += 128) {
        const int s = i / (15 * 37), rem = i % (15 * 37);
        qk2[s][49 + rem / 37][rem % 37] = make_float2(0.f, 0.f);
    }
    for (int i = tid; i < 32 * 15; i += 128)
        vt[i / 15][49 + i % 15] = 0.f;

    // ---- prologue: 2 threads per token, 16 dims each ----
    {
        const int tokr = tid >> 1;
        const bool act = tokr < NTOK;
        const int tok = act ? tokr : NTOK - 1;
        const int hf = tid & 1;
        // permuted token position for vt stores
        const int ptok = (tok & ~7) | (((tok & 3) << 1) | ((tok & 7) >> 2));
        const float* rp = &g_qkv[(size_t)(b * NTOK + tok) * 768 + h * HD + hf * 16];
        float qv[16], kv[16], vv[16];
#pragma unroll
        for (int i = 0; i < 4; ++i) {
            const float4 q4 = *(const float4*)&rp[i * 4];
            const float4 k4 = *(const float4*)&rp[256 + i * 4];
            const float4 v4 = *(const float4*)&rp[512 + i * 4];
            qv[i*4+0]=q4.x; qv[i*4+1]=q4.y; qv[i*4+2]=q4.z; qv[i*4+3]=q4.w;
            kv[i*4+0]=k4.x; kv[i*4+1]=k4.y; kv[i*4+2]=k4.z; kv[i*4+3]=k4.w;
            vv[i*4+0]=v4.x; vv[i*4+1]=v4.y; vv[i*4+2]=v4.z; vv[i*4+3]=v4.w;
        }
        float sq = 0.f, sk = 0.f;
#pragma unroll
        for (int i = 0; i < 16; ++i) {
            sq = fmaf(qv[i], qv[i], sq);
            sk = fmaf(kv[i], kv[i], sk);
        }
        sq += __shfl_xor_sync(0xffffffffu, sq, 1);
        sk += __shfl_xor_sync(0xffffffffu, sk, 1);
        const float qs = scale / fmaxf(sqrtf(sq), 1e-12f);
        const float ks = 1.f / fmaxf(sqrtf(sk), 1e-12f);
        if (act) {
#pragma unroll
            for (int i = 0; i < 16; ++i) {
                const int d = hf * 16 + i;
                const float qn = qv[i] * qs;
                const float kn = kv[i] * ks;
                const float qhi = tf32r(qn), khi = tf32r(kn);
                qk2[0][tok][d] = make_float2(qhi, tf32r(qn - qhi));
                qk2[1][tok][d] = make_float2(khi, tf32r(kn - khi));
                vt[d][ptok] = tf32r(vv[i]);
            }
        }
    }
    __syncthreads();

    // ---- QK^T (3xTF32), warp rows [wm, wm+16), all 64 cols ----
    float acc[8][4];
#pragma unroll
    for (int ni = 0; ni < 8; ++ni)
#pragma unroll
        for (int e = 0; e < 4; ++e) acc[ni][e] = 0.f;

#pragma unroll
    for (int ks = 0; ks < 4; ++ks) {
        const int kk = ks * 8;
        float2 aq[4];
        aq[0] = qk2[0][wm + g    ][kk + tg];
        aq[1] = qk2[0][wm + g + 8][kk + tg];
        aq[2] = qk2[0][wm + g    ][kk + tg + 4];
        aq[3] = qk2[0][wm + g + 8][kk + tg + 4];
        unsigned ah[4], al[4];
#pragma unroll
        for (int e = 0; e < 4; ++e) {
            ah[e] = __float_as_uint(aq[e].x);
            al[e] = __float_as_uint(aq[e].y);
        }
#pragma unroll
        for (int ni = 0; ni < 8; ++ni) {
            const int c = ni * 8 + g;
            const float2 b0 = qk2[1][c][kk + tg];
            const float2 b1 = qk2[1][c][kk + tg + 4];
            unsigned bh[2], bl[2];
            bh[0] = __float_as_uint(b0.x); bh[1] = __float_as_uint(b1.x);
            bl[0] = __float_as_uint(b0.y); bl[1] = __float_as_uint(b1.y);
            mma_tf32(acc[ni], ah, bh);
            mma_tf32(acc[ni], ah, bl);
            mma_tf32(acc[ni], al, bh);
        }
    }
    asm volatile("cp.async.wait_group 0;");   // bms resident
    __syncthreads();   // all warps done reading qk2; ps may overwrite it

    // ---- bias+mask add (aligned float2 from smem), pad masking ----
    const int r0 = wm + g, r1 = wm + g + 8;
    const int r0c = (r0 < 49) ? r0 : 48;    // clamp (pad rows discarded)
    const int r1c = (r1 < 49) ? r1 : 48;
    const float2* bp2 = (const float2*)bms;
#pragma unroll
    for (int ni = 0; ni < 8; ++ni) {
        const int c0 = ni * 8 + tg * 2;
        const float2 ba = bp2[r0c * 25 + ni * 4 + tg];
        const float2 bb2 = bp2[r1c * 25 + ni * 4 + tg];
        if (c0 < 49) { acc[ni][0] += ba.x; acc[ni][2] += bb2.x; }
        else { acc[ni][0] = -1e30f; acc[ni][2] = -1e30f; }
        if (c0 + 1 < 49) { acc[ni][1] += ba.y; acc[ni][3] += bb2.y; }
        else { acc[ni][1] = -1e30f; acc[ni][3] = -1e30f; }
    }

    // ---- softmax over 64 cols of rows r0, r1 ----
    float m0 = -1e30f, m1 = -1e30f;
#pragma unroll
    for (int ni = 0; ni < 8; ++ni) {
        m0 = fmaxf(m0, fmaxf(acc[ni][0], acc[ni][1]));
        m1 = fmaxf(m1, fmaxf(acc[ni][2], acc[ni][3]));
    }
    m0 = fmaxf(m0, __shfl_xor_sync(0xffffffffu, m0, 1));
    m0 = fmaxf(m0, __shfl_xor_sync(0xffffffffu, m0, 2));
    m1 = fmaxf(m1, __shfl_xor_sync(0xffffffffu, m1, 1));
    m1 = fmaxf(m1, __shfl_xor_sync(0xffffffffu, m1, 2));
    float s0 = 0.f, s1 = 0.f;
#pragma unroll
    for (int ni = 0; ni < 8; ++ni) {
        acc[ni][0] = __expf(acc[ni][0] - m0); s0 += acc[ni][0];
        acc[ni][1] = __expf(acc[ni][1] - m0); s0 += acc[ni][1];
        acc[ni][2] = __expf(acc[ni][2] - m1); s1 += acc[ni][2];
        acc[ni][3] = __expf(acc[ni][3] - m1); s1 += acc[ni][3];
    }
    s0 += __shfl_xor_sync(0xffffffffu, s0, 1);
    s0 += __shfl_xor_sync(0xffffffffu, s0, 2);
    s1 += __shfl_xor_sync(0xffffffffu, s1, 1);
    s1 += __shfl_xor_sync(0xffffffffu, s1, 2);
    const float i0 = 1.f / s0, i1 = 1.f / s1;
#pragma unroll
    for (int ni = 0; ni < 8; ++ni) {
        ps[r0 * 72 + ni * 8 + pp0] = tf32r(acc[ni][0] * i0);
        ps[r0 * 72 + ni * 8 + pp1] = tf32r(acc[ni][1] * i0);
        ps[r1 * 72 + ni * 8 + pp0] = tf32r(acc[ni][2] * i1);
        ps[r1 * 72 + ni * 8 + pp1] = tf32r(acc[ni][3] * i1);
    }
    __syncwarp();   // ps rows [wm,wm+16) written & read only by this warp

    // ---- AV: out[16 x 32] = P[16 x 64] @ V[64 x 32], LDS.64 fragments ----
    float oacc[4][4];
#pragma unroll
    for (int ni = 0; ni < 4; ++ni)
#pragma unroll
        for (int e = 0; e < 4; ++e) oacc[ni][e] = 0.f;

#pragma unroll
    for (int ks = 0; ks < 8; ++ks) {
        const int kk = ks * 8;
        const float2 aA = *(const float2*)&ps[(wm + g    ) * 72 + kk + tg * 2];
        const float2 aB = *(const float2*)&ps[(wm + g + 8) * 72 + kk + tg * 2];
        unsigned a[4];
        a[0] = __float_as_uint(aA.x);
        a[1] = __float_as_uint(aB.x);
        a[2] = __float_as_uint(aA.y);
        a[3] = __float_as_uint(aB.y);
#pragma unroll
        for (int ni = 0; ni < 4; ++ni) {
            const int c = ni * 8 + g;
            const float2 bv = *(const float2*)&vt[c][kk + tg * 2];
            unsigned bb[2];
            bb[0] = __float_as_uint(bv.x);
            bb[1] = __float_as_uint(bv.y);
            mma_tf32(oacc[ni], a, bb);
        }
    }

    // permuted tf32 store to g_att (layout proj expects)
    if (r0 < 49) {
        float* op = &g_att[(size_t)(b * NTOK + r0) * CDIM + h * HD];
#pragma unroll
        for (int ni = 0; ni < 4; ++ni) {
            op[ni * 8 + pp0] = tf32r(oacc[ni][0]);
            op[ni * 8 + pp1] = tf32r(oacc[ni][1]);
        }
    }
    if (r1 < 49) {
        float* op = &g_att[(size_t)(b * NTOK + r1) * CDIM + h * HD];
#pragma unroll
        for (int ni = 0; ni < 4; ++ni) {
            op[ni * 8 + pp0] = tf32r(oacc[ni][2]);
            op[ni * 8 + pp1] = tf32r(oacc[ni][3]);
        }
    }
}

// ---------------------------------------------------------------------------
extern "C" void kernel_launch(void* const* d_in, const int* in_sizes, int n_in,
                              void* d_out, int out_size)
{
    const float* x        = (const float*)d_in[0];
    const float* mask     = (const float*)d_in[1];
    const float* qkv_w    = (const float*)d_in[2];
    const float* q_bias   = (const float*)d_in[3];
    const float* v_bias   = (const float*)d_in[4];
    const float* logit_sc = (const float*)d_in[5];
    const float* cpb_w1   = (const float*)d_in[6];
    const float* cpb_b1   = (const float*)d_in[7];
    const float* cpb_w2   = (const float*)d_in[8];
    const float* proj_w   = (const float*)d_in[9];
    const float* proj_b   = (const float*)d_in[10];
    const float* table    = (const float*)d_in[11];
    const int*   rel_idx  = (const int*)d_in[12];

    const int B  = in_sizes[0] / (NTOK * CDIM);      // 2048
    const int nW = in_sizes[1] / NN2;                // 64
    const int M  = B * NTOK;                         // 100352

    round_x_kernel<<<2048, 256>>>(x, M * CDIM / 8);
    round_w_kernel<<<128, 256>>>(qkv_w, proj_w);
    mma_qkv<<<dim3(768 / 128, M / 128), 512>>>(q_bias, v_bias);
    cpb_kernel<<<169, 256>>>(table, cpb_w1, cpb_b1, cpb_w2);
    bm_kernel<<<nW * HEADS, 256>>>(mask, rel_idx);
    attn_mma<<<dim3(B, HEADS), 128>>>(logit_sc, nW);
    mma_proj<<<dim3(256 / 128, M / 128), 512>>>(proj_b, (float*)d_out);
}